// round 1
// baseline (speedup 1.0000x reference)
#include <cuda_runtime.h>
#include <cstdint>

// Problem shapes (fixed by setup_inputs)
#define B      4
#define NC     1024
#define NF     8192

#define TILE   128          // rows per tile AND cols per CTA
#define TPB    256          // 16x16 threads
#define ROWSPLIT 2          // CTAs per row dimension (each loops NF/ROWSPLIT rows)
#define NRED   148          // reduction CTAs

#define INF_BITS 0x7f800000u

// Scratch (allocation-free rule: __device__ globals)
__device__ unsigned int g_min1[B * NF];   // min over gt   for each ret_fine point (row mins)
__device__ unsigned int g_min2[B * NF];   // min over ret  for each gt_fine  point (col mins)
__device__ float        g_part[NRED * 3]; // per-CTA partial sums {s1, s2, s_coarse}

// ---------------------------------------------------------------------------
__global__ void init_mins_kernel() {
    int i = blockIdx.x * blockDim.x + threadIdx.x;
    if (i < B * NF) {
        g_min1[i] = INF_BITS;
        g_min2[i] = INF_BITS;
    }
}

// ---------------------------------------------------------------------------
// Fused pairwise-distance + dual min-reduction.
// grid: (NF/TILE, ROWSPLIT, B), block: 256 threads (16x16), micro-tile 8x8.
// X = ret_fine (rows, -> g_min1), Y = gt_fine (cols, -> g_min2).
__global__ __launch_bounds__(TPB) void chamfer_kernel(const float* __restrict__ X,
                                                      const float* __restrict__ Y) {
    __shared__ float4       sX[TILE];      // streamed row tile (x,y,z,|x|^2)
    __shared__ float4       sY[TILE];      // persistent col tile
    __shared__ float        sRow[TILE];    // per-tile row mins (one writer each)
    __shared__ unsigned int sCol[TILE];    // CTA col mins

    const int tid = threadIdx.x;
    const int tx  = tid & 15;              // 16 col-thread groups
    const int ty  = tid >> 4;              // 16 row-thread groups
    const int b   = blockIdx.z;
    const int colbase = blockIdx.x * TILE;
    const int row0    = blockIdx.y * (NF / ROWSPLIT);
    const int nTiles  = (NF / ROWSPLIT) / TILE;

    // Load persistent Y tile (+ squared norms), init col buffer
    if (tid < TILE) {
        int jg = b * NF + colbase + tid;
        float y0 = Y[jg * 3 + 0];
        float y1 = Y[jg * 3 + 1];
        float y2 = Y[jg * 3 + 2];
        sY[tid]  = make_float4(y0, y1, y2, fmaf(y0, y0, fmaf(y1, y1, y2 * y2)));
        sCol[tid] = INF_BITS;
    }
    __syncthreads();

    // Per-thread persistent column registers: 8 points
    float4 yr[8];
    float  cm[8];
#pragma unroll
    for (int j = 0; j < 8; ++j) {
        yr[j] = sY[tx * 8 + j];
        cm[j] = __int_as_float(0x7f800000);
    }

    for (int t = 0; t < nTiles; ++t) {
        const int r0 = row0 + t * TILE;
        if (tid < TILE) {
            int ig = b * NF + r0 + tid;
            float x0 = X[ig * 3 + 0];
            float x1 = X[ig * 3 + 1];
            float x2 = X[ig * 3 + 2];
            sX[tid]  = make_float4(x0, x1, x2, fmaf(x0, x0, fmaf(x1, x1, x2 * x2)));
        }
        __syncthreads();

#pragma unroll
        for (int i = 0; i < 8; ++i) {
            const float4 xp = sX[ty * 8 + i];
            float rm = __int_as_float(0x7f800000);
#pragma unroll
            for (int j = 0; j < 8; ++j) {
                float tdot = xp.x * yr[j].x;
                tdot = fmaf(xp.y, yr[j].y, tdot);
                tdot = fmaf(xp.z, yr[j].z, tdot);
                float d = fmaf(-2.0f, tdot, xp.w) + yr[j].w;
                rm    = fminf(rm, d);
                cm[j] = fminf(cm[j], d);
            }
            // reduce row-min across the 16 tx lanes (low 4 lane bits)
#pragma unroll
            for (int off = 1; off < 16; off <<= 1)
                rm = fminf(rm, __shfl_xor_sync(0xffffffffu, rm, off));
            if (tx == 0) sRow[ty * 8 + i] = rm;
        }
        __syncthreads();

        if (tid < TILE) {
            unsigned int bits = __float_as_uint(fmaxf(sRow[tid], 0.0f));
            atomicMin(&g_min1[b * NF + r0 + tid], bits);
        }
        // (no extra sync needed: next sX store is by the same guarded threads,
        //  and is ordered after this flush by the loop-top __syncthreads)
        __syncthreads();
    }

    // Flush column mins once per CTA
#pragma unroll
    for (int j = 0; j < 8; ++j)
        atomicMin(&sCol[tx * 8 + j], __float_as_uint(fmaxf(cm[j], 0.0f)));
    __syncthreads();
    if (tid < TILE)
        atomicMin(&g_min2[b * NF + colbase + tid], sCol[tid]);
}

// ---------------------------------------------------------------------------
// Partial sums: sqrt of the two min arrays + coarse L2 term.
__global__ __launch_bounds__(TPB) void reduce_kernel(const float* __restrict__ rc,
                                                     const float* __restrict__ gc) {
    __shared__ float sbuf[TPB];
    const int tid    = threadIdx.x;
    const int gstart = blockIdx.x * TPB + tid;
    const int stride = gridDim.x * TPB;

    float s1 = 0.0f, s2 = 0.0f, sc = 0.0f;
    for (int i = gstart; i < B * NF; i += stride)
        s1 += sqrtf(__uint_as_float(g_min1[i]));
    for (int i = gstart; i < B * NF; i += stride)
        s2 += sqrtf(__uint_as_float(g_min2[i]));
    for (int p = gstart; p < B * NC; p += stride) {
        float d0 = rc[p * 3 + 0] - gc[p * 3 + 0];
        float d1 = rc[p * 3 + 1] - gc[p * 3 + 1];
        float d2 = rc[p * 3 + 2] - gc[p * 3 + 2];
        sc += sqrtf(fmaf(d0, d0, fmaf(d1, d1, d2 * d2)));
    }

    // three deterministic block tree-reductions
    float vals[3] = {s1, s2, sc};
#pragma unroll
    for (int k = 0; k < 3; ++k) {
        sbuf[tid] = vals[k];
        __syncthreads();
        for (int off = TPB / 2; off > 0; off >>= 1) {
            if (tid < off) sbuf[tid] += sbuf[tid + off];
            __syncthreads();
        }
        if (tid == 0) g_part[blockIdx.x * 3 + k] = sbuf[0];
        __syncthreads();
    }
}

__global__ void final_kernel(float* __restrict__ out) {
    if (threadIdx.x == 0 && blockIdx.x == 0) {
        float s1 = 0.0f, s2 = 0.0f, sc = 0.0f;
        for (int c = 0; c < NRED; ++c) {
            s1 += g_part[c * 3 + 0];
            s2 += g_part[c * 3 + 1];
            sc += g_part[c * 3 + 2];
        }
        const float invBN = 1.0f / (float)(B * NF);
        out[0] = sc / (float)(B * NC);                  // loss_coarse
        out[1] = 0.5f * (s1 * invBN + s2 * invBN);      // loss_fine
    }
}

// ---------------------------------------------------------------------------
extern "C" void kernel_launch(void* const* d_in, const int* in_sizes, int n_in,
                              void* d_out, int out_size) {
    const float* ret_coarse = (const float*)d_in[0];
    const float* ret_fine   = (const float*)d_in[1];
    const float* gt_fine    = (const float*)d_in[2];
    const float* gt_coarse  = (const float*)d_in[3];
    float* out = (float*)d_out;

    init_mins_kernel<<<(B * NF + TPB - 1) / TPB, TPB>>>();

    dim3 grid(NF / TILE, ROWSPLIT, B);   // (64, 2, 4) = 512 CTAs
    chamfer_kernel<<<grid, TPB>>>(ret_fine, gt_fine);

    reduce_kernel<<<NRED, TPB>>>(ret_coarse, gt_coarse);
    final_kernel<<<1, 32>>>(out);
}

// round 2
// speedup vs baseline: 1.3580x; 1.3580x over previous
#include <cuda_runtime.h>
#include <cstdint>

// Problem shapes (fixed by setup_inputs)
#define B      4
#define NC     1024
#define NF     8192

#define TILE   128          // rows per tile AND cols per CTA
#define TPB    256          // 16x16 threads
#define ROWSPLIT 2          // CTAs splitting the row dimension
#define NRED   148          // reduction CTAs

#define INF_BITS 0x7f800000u
#define PADW   18           // sPart row pad: 8*18 mod 32 = 16 -> conflict-free STS

typedef unsigned long long u64;

// Scratch (allocation-free rule: __device__ globals)
__device__ unsigned int g_min1[B * NF];   // min over gt   for each ret_fine point (rows)
__device__ unsigned int g_min2[B * NF];   // min over ret  for each gt_fine  point (cols)
__device__ float        g_part[NRED * 3]; // per-CTA partial sums {s1, s2, s_coarse}

// ---- packed f32x2 helpers (sm_103a) ---------------------------------------
__device__ __forceinline__ u64 pk(float lo, float hi) {
    u64 r; asm("mov.b64 %0, {%1, %2};" : "=l"(r) : "f"(lo), "f"(hi)); return r;
}
__device__ __forceinline__ void upk(float& lo, float& hi, u64 v) {
    asm("mov.b64 {%0, %1}, %2;" : "=f"(lo), "=f"(hi) : "l"(v));
}
__device__ __forceinline__ u64 fma2(u64 a, u64 b, u64 c) {
    u64 d; asm("fma.rn.f32x2 %0, %1, %2, %3;" : "=l"(d) : "l"(a), "l"(b), "l"(c)); return d;
}
__device__ __forceinline__ u64 add2(u64 a, u64 b) {
    u64 d; asm("add.rn.f32x2 %0, %1, %2;" : "=l"(d) : "l"(a), "l"(b)); return d;
}

// ---------------------------------------------------------------------------
__global__ void init_mins_kernel() {
    int i = blockIdx.x * blockDim.x + threadIdx.x;
    if (i < B * NF) {
        g_min1[i] = INF_BITS;
        g_min2[i] = INF_BITS;
    }
}

// ---------------------------------------------------------------------------
// Fused pairwise-distance + dual min-reduction.
// grid: (NF/TILE, ROWSPLIT, B), block 16x16, micro-tile 8x8 (cols packed 2-wide).
// X = ret_fine (rows -> g_min1), Y = gt_fine (cols -> g_min2).
__global__ __launch_bounds__(TPB, 4) void chamfer_kernel(const float* __restrict__ X,
                                                         const float* __restrict__ Y) {
    __shared__ float4       sX[TILE];          // streamed row tile (x,y,z,|x|^2); Y staging first
    __shared__ float        sPart[TILE][PADW]; // per-(row, tx) partial row mins
    __shared__ unsigned int sCol[TILE];        // CTA col mins

    const int tid = threadIdx.x;
    const int tx  = tid & 15;              // 16 col-thread groups (8 cols each)
    const int ty  = tid >> 4;              // 16 row-thread groups (8 rows each)
    const int b   = blockIdx.z;
    const int colbase = blockIdx.x * TILE;
    const int row0    = blockIdx.y * (NF / ROWSPLIT);
    const int nTiles  = (NF / ROWSPLIT) / TILE;

    // Stage Y tile through sX: (-2x, -2y, -2z, |y|^2)
    if (tid < TILE) {
        int jg = b * NF + colbase + tid;
        float y0 = Y[jg * 3 + 0];
        float y1 = Y[jg * 3 + 1];
        float y2 = Y[jg * 3 + 2];
        sX[tid]  = make_float4(-2.0f * y0, -2.0f * y1, -2.0f * y2,
                               fmaf(y0, y0, fmaf(y1, y1, y2 * y2)));
        sCol[tid] = INF_BITS;
    }
    __syncthreads();

    // Persistent packed column registers: 8 cols as 4 f32x2 groups
    u64 ya[4], yb[4], yc[4], yw[4];
    float cm[8];
#pragma unroll
    for (int g = 0; g < 4; ++g) {
        float4 p = sX[tx * 8 + 2 * g];
        float4 q = sX[tx * 8 + 2 * g + 1];
        ya[g] = pk(p.x, q.x);
        yb[g] = pk(p.y, q.y);
        yc[g] = pk(p.z, q.z);
        yw[g] = pk(p.w, q.w);
        cm[2 * g]     = __int_as_float(0x7f800000);
        cm[2 * g + 1] = __int_as_float(0x7f800000);
    }
    __syncthreads();   // done staging Y through sX

    for (int t = 0; t < nTiles; ++t) {
        const int r0 = row0 + t * TILE;
        if (tid < TILE) {
            int ig = b * NF + r0 + tid;
            float x0 = X[ig * 3 + 0];
            float x1 = X[ig * 3 + 1];
            float x2 = X[ig * 3 + 2];
            sX[tid]  = make_float4(x0, x1, x2, fmaf(x0, x0, fmaf(x1, x1, x2 * x2)));
        }
        __syncthreads();   // sync A

#pragma unroll
        for (int i = 0; i < 8; ++i) {
            const float4 xp = sX[ty * 8 + i];
            const u64 bx = pk(xp.x, xp.x);
            const u64 by = pk(xp.y, xp.y);
            const u64 bz = pk(xp.z, xp.z);
            const u64 bw = pk(xp.w, xp.w);
            float rml = __int_as_float(0x7f800000);
            float rmh = __int_as_float(0x7f800000);
#pragma unroll
            for (int g = 0; g < 4; ++g) {
                // d = |x|^2 + |y|^2 - 2 x.y   (y pre-scaled by -2, |y|^2 pre-folded)
                u64 e = add2(yw[g], bw);
                e = fma2(yc[g], bz, e);
                e = fma2(yb[g], by, e);
                e = fma2(ya[g], bx, e);
                float dl, dh;
                upk(dl, dh, e);
                rml = fminf(rml, dl);
                rmh = fminf(rmh, dh);
                cm[2 * g]     = fminf(cm[2 * g],     dl);
                cm[2 * g + 1] = fminf(cm[2 * g + 1], dh);
            }
            sPart[ty * 8 + i][tx] = fminf(rml, rmh);
        }
        __syncthreads();   // sync B

        if (tid < TILE) {
            float m = sPart[tid][0];
#pragma unroll
            for (int c = 1; c < 16; ++c) m = fminf(m, sPart[tid][c]);
            atomicMin(&g_min1[b * NF + r0 + tid], __float_as_uint(fmaxf(m, 0.0f)));
        }
        // loop-top sync A orders sPart rewrite after these reads
    }

    // Flush column mins once per CTA
#pragma unroll
    for (int j = 0; j < 8; ++j)
        atomicMin(&sCol[tx * 8 + j], __float_as_uint(fmaxf(cm[j], 0.0f)));
    __syncthreads();
    if (tid < TILE)
        atomicMin(&g_min2[b * NF + colbase + tid], sCol[tid]);
}

// ---------------------------------------------------------------------------
// Partial sums: sqrt of the two min arrays + coarse L2 term.
__global__ __launch_bounds__(TPB) void reduce_kernel(const float* __restrict__ rc,
                                                     const float* __restrict__ gc) {
    __shared__ float sbuf[TPB];
    const int tid    = threadIdx.x;
    const int gstart = blockIdx.x * TPB + tid;
    const int stride = gridDim.x * TPB;

    float s1 = 0.0f, s2 = 0.0f, sc = 0.0f;
    for (int i = gstart; i < B * NF; i += stride)
        s1 += sqrtf(__uint_as_float(g_min1[i]));
    for (int i = gstart; i < B * NF; i += stride)
        s2 += sqrtf(__uint_as_float(g_min2[i]));
    for (int p = gstart; p < B * NC; p += stride) {
        float d0 = rc[p * 3 + 0] - gc[p * 3 + 0];
        float d1 = rc[p * 3 + 1] - gc[p * 3 + 1];
        float d2 = rc[p * 3 + 2] - gc[p * 3 + 2];
        sc += sqrtf(fmaf(d0, d0, fmaf(d1, d1, d2 * d2)));
    }

    float vals[3] = {s1, s2, sc};
#pragma unroll
    for (int k = 0; k < 3; ++k) {
        sbuf[tid] = vals[k];
        __syncthreads();
        for (int off = TPB / 2; off > 0; off >>= 1) {
            if (tid < off) sbuf[tid] += sbuf[tid + off];
            __syncthreads();
        }
        if (tid == 0) g_part[blockIdx.x * 3 + k] = sbuf[0];
        __syncthreads();
    }
}

// Parallel final combine (was a 12.6us serial loop).
__global__ void final_kernel(float* __restrict__ out) {
    __shared__ float r1[TPB], r2[TPB], r3[TPB];
    const int tid = threadIdx.x;
    float s1 = 0.0f, s2 = 0.0f, sc = 0.0f;
    for (int c = tid; c < NRED; c += TPB) {
        s1 += g_part[c * 3 + 0];
        s2 += g_part[c * 3 + 1];
        sc += g_part[c * 3 + 2];
    }
    r1[tid] = s1; r2[tid] = s2; r3[tid] = sc;
    __syncthreads();
    for (int off = TPB / 2; off > 0; off >>= 1) {
        if (tid < off) {
            r1[tid] += r1[tid + off];
            r2[tid] += r2[tid + off];
            r3[tid] += r3[tid + off];
        }
        __syncthreads();
    }
    if (tid == 0) {
        const float invBN = 1.0f / (float)(B * NF);
        out[0] = r3[0] / (float)(B * NC);                 // loss_coarse
        out[1] = 0.5f * (r1[0] * invBN + r2[0] * invBN);  // loss_fine
    }
}

// ---------------------------------------------------------------------------
extern "C" void kernel_launch(void* const* d_in, const int* in_sizes, int n_in,
                              void* d_out, int out_size) {
    const float* ret_coarse = (const float*)d_in[0];
    const float* ret_fine   = (const float*)d_in[1];
    const float* gt_fine    = (const float*)d_in[2];
    const float* gt_coarse  = (const float*)d_in[3];
    float* out = (float*)d_out;

    init_mins_kernel<<<(B * NF + TPB - 1) / TPB, TPB>>>();

    dim3 grid(NF / TILE, ROWSPLIT, B);   // (64, 2, 4) = 512 CTAs, 1 wave @ occ 4
    chamfer_kernel<<<grid, TPB>>>(ret_fine, gt_fine);

    reduce_kernel<<<NRED, TPB>>>(ret_coarse, gt_coarse);
    final_kernel<<<1, TPB>>>(out);
}